// round 9
// baseline (speedup 1.0000x reference)
#include <cuda_runtime.h>
#include <cuda_fp16.h>
#include <math_constants.h>
#include <cstdint>

// Problem constants
#define S2    2048
#define HID   1024
#define NH    16
#define HD    64
#define BATCH 2

// Scratch for projected Q and V in [B, H, S, d] layout (16 MB each).
__device__ float g_q[BATCH * NH * S2 * HD];
__device__ float g_v[BATCH * NH * S2 * HD];

// ---------------------------------------------------------------------------
// FP16 tensor-core projection GEMM (measured ~47us for both projections).
// ---------------------------------------------------------------------------
#define PKB 32
#define AKP 40
#define BNP 136

__device__ __forceinline__ uint2 f4_to_h4(float4 v) {
    __half2 h0 = __floats2half2_rn(v.x, v.y);
    __half2 h1 = __floats2half2_rn(v.z, v.w);
    uint2 r;
    r.x = *(uint32_t*)&h0;
    r.y = *(uint32_t*)&h1;
    return r;
}

__device__ __forceinline__ void ldsm_x4(uint32_t& r0, uint32_t& r1,
                                        uint32_t& r2, uint32_t& r3,
                                        const __half* p) {
    uint32_t a = (uint32_t)__cvta_generic_to_shared(p);
    asm volatile("ldmatrix.sync.aligned.m8n8.x4.shared.b16 {%0,%1,%2,%3}, [%4];"
                 : "=r"(r0), "=r"(r1), "=r"(r2), "=r"(r3) : "r"(a));
}

__device__ __forceinline__ void ldsm_x2_trans(uint32_t& r0, uint32_t& r1,
                                              const __half* p) {
    uint32_t a = (uint32_t)__cvta_generic_to_shared(p);
    asm volatile("ldmatrix.sync.aligned.m8n8.x2.trans.shared.b16 {%0,%1}, [%2];"
                 : "=r"(r0), "=r"(r1) : "r"(a));
}

__device__ __forceinline__ void mma_f16(float c[4], const uint32_t a[4],
                                        const uint32_t b[2]) {
    asm volatile(
        "mma.sync.aligned.m16n8k16.row.col.f32.f16.f16.f32 "
        "{%0,%1,%2,%3}, {%4,%5,%6,%7}, {%8,%9}, {%0,%1,%2,%3};"
        : "+f"(c[0]), "+f"(c[1]), "+f"(c[2]), "+f"(c[3])
        : "r"(a[0]), "r"(a[1]), "r"(a[2]), "r"(a[3]), "r"(b[0]), "r"(b[1]));
}

__global__ __launch_bounds__(256)
void proj_kernel(const float* __restrict__ A,
                 const float* __restrict__ Wq, const float* __restrict__ bq,
                 const float* __restrict__ Wv, const float* __restrict__ bv)
{
    const float* __restrict__ W    = blockIdx.z ? Wv : Wq;
    const float* __restrict__ bias = blockIdx.z ? bv : bq;
    float* __restrict__ out        = blockIdx.z ? g_v : g_q;

    __shared__ __half As[2][128][AKP];
    __shared__ __half Bs[2][PKB][BNP];

    const int tid  = threadIdx.x;
    const int lane = tid & 31;
    const int wid  = tid >> 5;
    const int gid  = lane >> 2;
    const int tig  = lane & 3;
    const int m0   = blockIdx.y * 128;
    const int n0   = blockIdx.x * 128;

    const int mBase = (wid >> 2) * 64;
    const int nBase = (wid & 3) * 32;

    const int a_row = (lane & 7) + 8 * ((lane >> 3) & 1);
    const int a_col = 8 * (lane >> 4);
    const int b_row = lane & 15;

    float c[4][4][4];
    #pragma unroll
    for (int f = 0; f < 4; f++)
        #pragma unroll
        for (int g = 0; g < 4; g++)
            #pragma unroll
            for (int i = 0; i < 4; i++) c[f][g][i] = 0.0f;

    uint2 pa[4], pb[4];

    #pragma unroll
    for (int p = 0; p < 4; p++) {
        int s = tid + 256 * p;
        int m = s >> 3, kq = s & 7;
        pa[p] = f4_to_h4(*(const float4*)(A + (size_t)(m0 + m) * HID + 4 * kq));
        int kr = s >> 5, nq = s & 31;
        pb[p] = f4_to_h4(*(const float4*)(W + (size_t)kr * HID + n0 + 4 * nq));
    }
    #pragma unroll
    for (int p = 0; p < 4; p++) {
        int s = tid + 256 * p;
        int m = s >> 3, kq = s & 7;
        *(uint2*)&As[0][m][4 * kq] = pa[p];
        int kr = s >> 5, nq = s & 31;
        *(uint2*)&Bs[0][kr][4 * nq] = pb[p];
    }
    __syncthreads();

    const int NKB = HID / PKB;
    for (int kb = 0; kb < NKB; kb++) {
        const int cur = kb & 1;
        const int nxt = cur ^ 1;

        if (kb + 1 < NKB) {
            const int kk = (kb + 1) * PKB;
            #pragma unroll
            for (int p = 0; p < 4; p++) {
                int s = tid + 256 * p;
                int m = s >> 3, kq = s & 7;
                pa[p] = f4_to_h4(*(const float4*)(A + (size_t)(m0 + m) * HID + kk + 4 * kq));
                int kr = s >> 5, nq = s & 31;
                pb[p] = f4_to_h4(*(const float4*)(W + (size_t)(kk + kr) * HID + n0 + 4 * nq));
            }
        }

        #pragma unroll
        for (int ks = 0; ks < PKB; ks += 16) {
            uint32_t a[4][4], b[4][2];
            #pragma unroll
            for (int f = 0; f < 4; f++)
                ldsm_x4(a[f][0], a[f][1], a[f][2], a[f][3],
                        &As[cur][mBase + 16 * f + a_row][ks + a_col]);
            #pragma unroll
            for (int g = 0; g < 4; g++)
                ldsm_x2_trans(b[g][0], b[g][1],
                              &Bs[cur][ks + b_row][nBase + 8 * g]);
            #pragma unroll
            for (int f = 0; f < 4; f++)
                #pragma unroll
                for (int g = 0; g < 4; g++)
                    mma_f16(c[f][g], a[f], b[g]);
        }

        if (kb + 1 < NKB) {
            #pragma unroll
            for (int p = 0; p < 4; p++) {
                int s = tid + 256 * p;
                int m = s >> 3, kq = s & 7;
                *(uint2*)&As[nxt][m][4 * kq] = pa[p];
                int kr = s >> 5, nq = s & 31;
                *(uint2*)&Bs[nxt][kr][4 * nq] = pb[p];
            }
        }
        __syncthreads();
    }

    #pragma unroll
    for (int g = 0; g < 4; g++) {
        const int n  = n0 + nBase + 8 * g + 2 * tig;
        const int h  = n >> 6;
        const int cc = n & 63;
        const float b0 = bias[n];
        const float b1 = bias[n + 1];
        #pragma unroll
        for (int f = 0; f < 4; f++) {
            #pragma unroll
            for (int half = 0; half < 2; half++) {
                int m  = m0 + mBase + 16 * f + gid + 8 * half;
                int bb = m >> 11;
                int s  = m & 2047;
                float2 o;
                o.x = c[f][g][2 * half + 0] + b0;
                o.y = c[f][g][2 * half + 1] + b1;
                *(float2*)(out + (((size_t)(bb * NH + h) * S2 + s) * HD + cc)) = o;
            }
        }
    }
}

// ---------------------------------------------------------------------------
// Tiled sparse attention — fp16 K/V tiles, 4 CTAs/SM.
// Kh: fp16 K transposed [d][170] (pitch 170 halves: 85 odd -> staging stores
//     AND half2 score loads conflict-free). Aliased by V fp16 [c][64].
// Qs: fp32 [d][36] (float4 broadcast in score GEMM); aliased by Cstr [r][66].
// Ps: fp32 [32][168]; Sstr fp32 [32][16].
// smem = 21760 + 9216 + 21504 + 2048 = 54,528 B -> 4 CTAs/SM.
// Masked entries are exactly 0 after softmax (fp32 exp underflow) -> exact.
// ---------------------------------------------------------------------------
#define TQ    32
#define WIN   160
#define KP2   170   // K fp16 pitch (halves)
#define QPAD  36
#define PSW   168
#define CPAD  66

#define ATTN_SMEM_BYTES (64*KP2*2 + 64*QPAD*4 + TQ*PSW*4 + TQ*16*4)

__global__ __launch_bounds__(256, 4)
void attn_kernel(const float* __restrict__ amask, float* __restrict__ out)
{
    extern __shared__ float sm[];
    __half* Kh  = (__half*)sm;               // [64][170] fp16; union V [160][64]
    float* QC   = sm + (64 * KP2 * 2) / 4;   // Qs [64][36] then Cstr [32][66]
    float* Ps   = QC + 64 * QPAD;            // [32][168]
    float* Sstr = Ps + TQ * PSW;             // [32][16]
    float* Qs   = QC;
    float* Cstr = QC;

    const int tid = threadIdx.x;
    const int tx  = tid & 31;
    const int ty  = tid >> 5;
    const int I0  = blockIdx.x * TQ;
    const int bh  = blockIdx.y;
    const int b   = bh >> 4;
    const int jbase = I0 - 128;

    const float* __restrict__ q  = g_q + (size_t)bh * S2 * HD;
    const float* __restrict__ v  = g_v + (size_t)bh * S2 * HD;
    const float* __restrict__ am = amask + b * S2;

    // ---- stage Q (fp32 transposed [d][36]) and K (fp16 transposed [d][170]) ----
    for (int idx = tid; idx < TQ * HD; idx += 256) {
        int r = idx >> 6, d = idx & 63;
        Qs[d * QPAD + r] = q[(size_t)(I0 + r) * HD + d];
    }
    for (int idx = tid; idx < WIN * HD; idx += 256) {
        int c = idx >> 6, d = idx & 63;
        int j = jbase + c;
        float val = (j >= 0) ? q[(size_t)j * HD + d] : 0.0f;
        Kh[d * KP2 + c] = __float2half(val);
    }
    __syncthreads();

    // ---- dense score GEMM: 4 queries x 6 keys (3 x half2) per thread ----
    float2 acc[4][3];
    #pragma unroll
    for (int qi = 0; qi < 4; qi++)
        #pragma unroll
        for (int u = 0; u < 3; u++) acc[qi][u] = make_float2(0.f, 0.f);

    const bool tail = (tx < 16);
    #pragma unroll 8
    for (int d = 0; d < 64; d++) {
        float4 a4 = *(const float4*)&Qs[d * QPAD + 4 * ty];
        float aq[4] = {a4.x, a4.y, a4.z, a4.w};
        #pragma unroll
        for (int u = 0; u < 3; u++) {
            if (u == 2 && !tail) break;
            __half2 kh = *(const __half2*)&Kh[d * KP2 + 2 * (tx + 32 * u)];
            float2 kf = __half22float2(kh);
            #pragma unroll
            for (int qi = 0; qi < 4; qi++) {
                acc[qi][u].x = fmaf(aq[qi], kf.x, acc[qi][u].x);
                acc[qi][u].y = fmaf(aq[qi], kf.y, acc[qi][u].y);
            }
        }
    }

    // mask + scale + attention_mask -> Ps row-major [r][c], float2 stores
    #pragma unroll
    for (int u = 0; u < 3; u++) {
        if (u == 2 && !tail) break;
        int c0 = 2 * (tx + 32 * u);
        int j0 = jbase + c0;
        float am0 = (j0 >= 0) ? am[j0] : 0.0f;
        float am1 = (j0 + 1 >= 0) ? am[j0 + 1] : 0.0f;
        #pragma unroll
        for (int qi = 0; qi < 4; qi++) {
            int r = ty * 4 + qi;
            bool ok0 = (c0 >= r) && (c0 <= r + 128) && (j0 >= 0);
            bool ok1 = (c0 + 1 >= r) && (c0 + 1 <= r + 128) && (j0 + 1 >= 0);
            float2 sv;
            sv.x = ok0 ? (acc[qi][u].x * 0.125f + am0) : -CUDART_INF_F;
            sv.y = ok1 ? (acc[qi][u].y * 0.125f + am1) : -CUDART_INF_F;
            *(float2*)&Ps[r * PSW + c0] = sv;
        }
    }
    __syncthreads();   // K reads done -> safe to overwrite Kh with V

    // ---- stage V fp16 row-major [c][64] (float2 -> half2, coalesced) ----
    for (int idx = tid; idx < WIN * 32; idx += 256) {
        int c = idx >> 5, dq = idx & 31;
        int j = jbase + c;
        float2 val = (j >= 0) ? *(const float2*)(v + (size_t)j * HD + 2 * dq)
                              : make_float2(0.f, 0.f);
        *(__half2*)&Kh[c * HD + 2 * dq] = __float22half2_rn(val);
    }

    // ---- strided scores (t >= 2): last use of Qs; float2 gmem gathers ----
    #pragma unroll
    for (int qi = 0; qi < 4; qi++) {
        int r = ty * 4 + qi;
        int i = I0 + r;
        int nstr = i >> 7;
        float qa = Qs[(2 * tx) * QPAD + r];
        float qb = Qs[(2 * tx + 1) * QPAD + r];
        for (int t = 2; t <= nstr; t++) {
            int j = i - (t << 7);
            float2 k2 = *(const float2*)(q + (size_t)j * HD + 2 * tx);
            float p = qa * k2.x + qb * k2.y;
            p += __shfl_xor_sync(0xffffffffu, p, 16);
            p += __shfl_xor_sync(0xffffffffu, p, 8);
            p += __shfl_xor_sync(0xffffffffu, p, 4);
            p += __shfl_xor_sync(0xffffffffu, p, 2);
            p += __shfl_xor_sync(0xffffffffu, p, 1);
            if (tx == 0) Sstr[r * 16 + t] = p * 0.125f + am[j];
        }
    }
    __syncthreads();   // Qs dead everywhere -> Cstr may alias it

    // ---- softmax + strided ctx (writes Cstr over old Qs) ----
    #pragma unroll
    for (int qi = 0; qi < 4; qi++) {
        int r = ty * 4 + qi;
        int i = I0 + r;
        int nstr = i >> 7;

        float mx = -CUDART_INF_F;
        #pragma unroll
        for (int u = 0; u < 5; u++) mx = fmaxf(mx, Ps[r * PSW + tx + 32 * u]);
        if (tx + 2 <= nstr) mx = fmaxf(mx, Sstr[r * 16 + tx + 2]);
        mx = fmaxf(mx, __shfl_xor_sync(0xffffffffu, mx, 16));
        mx = fmaxf(mx, __shfl_xor_sync(0xffffffffu, mx, 8));
        mx = fmaxf(mx, __shfl_xor_sync(0xffffffffu, mx, 4));
        mx = fmaxf(mx, __shfl_xor_sync(0xffffffffu, mx, 2));
        mx = fmaxf(mx, __shfl_xor_sync(0xffffffffu, mx, 1));

        float s = 0.0f;
        float e[5];
        #pragma unroll
        for (int u = 0; u < 5; u++) {
            e[u] = __expf(Ps[r * PSW + tx + 32 * u] - mx);
            s += e[u];
        }
        float es = 0.0f;
        if (tx + 2 <= nstr) es = __expf(Sstr[r * 16 + tx + 2] - mx);
        s += es;
        s += __shfl_xor_sync(0xffffffffu, s, 16);
        s += __shfl_xor_sync(0xffffffffu, s, 8);
        s += __shfl_xor_sync(0xffffffffu, s, 4);
        s += __shfl_xor_sync(0xffffffffu, s, 2);
        s += __shfl_xor_sync(0xffffffffu, s, 1);
        float inv = 1.0f / s;

        #pragma unroll
        for (int u = 0; u < 5; u++) Ps[r * PSW + tx + 32 * u] = e[u] * inv;

        float ax = 0.0f, ay = 0.0f;
        float pn = es * inv;
        for (int t = 2; t <= nstr; t++) {
            float p = __shfl_sync(0xffffffffu, pn, t - 2);
            int j = i - (t << 7);
            float2 v2 = *(const float2*)(v + (size_t)j * HD + 2 * tx);
            ax = fmaf(p, v2.x, ax);
            ay = fmaf(p, v2.y, ay);
        }
        float2 cst; cst.x = ax; cst.y = ay;
        *(float2*)&Cstr[r * CPAD + 2 * tx] = cst;   // d = 2tx, 2tx+1
    }
    __syncthreads();   // V staged + Ps normalized + Cstr written

    // ---- dense ctx GEMM: 4 queries x 2 d-cols, keys in groups of 4 ----
    float o[4][2];
    #pragma unroll
    for (int qi = 0; qi < 4; qi++) { o[qi][0] = 0.0f; o[qi][1] = 0.0f; }

    #pragma unroll 2
    for (int c4 = 0; c4 < WIN / 4; c4++) {
        float2 v0 = __half22float2(*(const __half2*)&Kh[(4 * c4 + 0) * HD + 2 * tx]);
        float2 v1 = __half22float2(*(const __half2*)&Kh[(4 * c4 + 1) * HD + 2 * tx]);
        float2 v2 = __half22float2(*(const __half2*)&Kh[(4 * c4 + 2) * HD + 2 * tx]);
        float2 v3 = __half22float2(*(const __half2*)&Kh[(4 * c4 + 3) * HD + 2 * tx]);
        #pragma unroll
        for (int qi = 0; qi < 4; qi++) {
            float4 pp = *(const float4*)&Ps[(4 * ty + qi) * PSW + 4 * c4];
            o[qi][0] = fmaf(pp.x, v0.x, o[qi][0]);
            o[qi][0] = fmaf(pp.y, v1.x, o[qi][0]);
            o[qi][0] = fmaf(pp.z, v2.x, o[qi][0]);
            o[qi][0] = fmaf(pp.w, v3.x, o[qi][0]);
            o[qi][1] = fmaf(pp.x, v0.y, o[qi][1]);
            o[qi][1] = fmaf(pp.y, v1.y, o[qi][1]);
            o[qi][1] = fmaf(pp.z, v2.y, o[qi][1]);
            o[qi][1] = fmaf(pp.w, v3.y, o[qi][1]);
        }
    }

    // ---- epilogue: add strided ctx, store [B, S, H*64] ----
    #pragma unroll
    for (int qi = 0; qi < 4; qi++) {
        int r = ty * 4 + qi;
        int i = I0 + r;
        float2 cs = *(const float2*)&Cstr[r * CPAD + 2 * tx];
        float2 res;
        res.x = o[qi][0] + cs.x;
        res.y = o[qi][1] + cs.y;
        *(float2*)(out + ((size_t)(b * S2 + i) * (NH * HD)) + (bh & 15) * HD + 2 * tx) = res;
    }
}

// ---------------------------------------------------------------------------
// Launch
// Inputs (metadata order): hidden_states, attention_mask, W_q, b_q, W_v, b_v
// ---------------------------------------------------------------------------
extern "C" void kernel_launch(void* const* d_in, const int* in_sizes, int n_in,
                              void* d_out, int out_size)
{
    const float* hidden = (const float*)d_in[0];
    const float* amask  = (const float*)d_in[1];
    const float* Wq     = (const float*)d_in[2];
    const float* bq     = (const float*)d_in[3];
    const float* Wv     = (const float*)d_in[4];
    const float* bv     = (const float*)d_in[5];
    float* out = (float*)d_out;

    cudaFuncSetAttribute(attn_kernel,
                         cudaFuncAttributeMaxDynamicSharedMemorySize,
                         ATTN_SMEM_BYTES);

    dim3 pgrid(HID / 128, (BATCH * S2) / 128, 2);   // (8, 32, 2)
    proj_kernel<<<pgrid, 256>>>(hidden, Wq, bq, Wv, bv);

    dim3 agrid(S2 / TQ, BATCH * NH);                // (64, 32)
    attn_kernel<<<agrid, 256, ATTN_SMEM_BYTES>>>(amask, out);
}

// round 10
// speedup vs baseline: 1.3285x; 1.3285x over previous
#include <cuda_runtime.h>
#include <cuda_fp16.h>
#include <math_constants.h>
#include <cstdint>

// Problem constants
#define S2    2048
#define HID   1024
#define NH    16
#define HD    64
#define BATCH 2

// Scratch for projected Q and V in [B, H, S, d] layout (16 MB each).
__device__ float g_q[BATCH * NH * S2 * HD];
__device__ float g_v[BATCH * NH * S2 * HD];

// ---------------------------------------------------------------------------
// Shared mma/ldmatrix helpers (validated in the proj kernel since round 5).
// ---------------------------------------------------------------------------
__device__ __forceinline__ uint2 f4_to_h4(float4 v) {
    __half2 h0 = __floats2half2_rn(v.x, v.y);
    __half2 h1 = __floats2half2_rn(v.z, v.w);
    uint2 r;
    r.x = *(uint32_t*)&h0;
    r.y = *(uint32_t*)&h1;
    return r;
}

__device__ __forceinline__ void ldsm_x4(uint32_t& r0, uint32_t& r1,
                                        uint32_t& r2, uint32_t& r3,
                                        const __half* p) {
    uint32_t a = (uint32_t)__cvta_generic_to_shared(p);
    asm volatile("ldmatrix.sync.aligned.m8n8.x4.shared.b16 {%0,%1,%2,%3}, [%4];"
                 : "=r"(r0), "=r"(r1), "=r"(r2), "=r"(r3) : "r"(a));
}

__device__ __forceinline__ void ldsm_x2_trans(uint32_t& r0, uint32_t& r1,
                                              const __half* p) {
    uint32_t a = (uint32_t)__cvta_generic_to_shared(p);
    asm volatile("ldmatrix.sync.aligned.m8n8.x2.trans.shared.b16 {%0,%1}, [%2];"
                 : "=r"(r0), "=r"(r1) : "r"(a));
}

__device__ __forceinline__ void mma_f16(float c[4], const uint32_t a[4],
                                        const uint32_t b[2]) {
    asm volatile(
        "mma.sync.aligned.m16n8k16.row.col.f32.f16.f16.f32 "
        "{%0,%1,%2,%3}, {%4,%5,%6,%7}, {%8,%9}, {%0,%1,%2,%3};"
        : "+f"(c[0]), "+f"(c[1]), "+f"(c[2]), "+f"(c[3])
        : "r"(a[0]), "r"(a[1]), "r"(a[2]), "r"(a[3]), "r"(b[0]), "r"(b[1]));
}

// ---------------------------------------------------------------------------
// FP16 tensor-core projection GEMM (measured ~47us for both projections).
// ---------------------------------------------------------------------------
#define PKB 32
#define AKP 40
#define BNP 136

__global__ __launch_bounds__(256)
void proj_kernel(const float* __restrict__ A,
                 const float* __restrict__ Wq, const float* __restrict__ bq,
                 const float* __restrict__ Wv, const float* __restrict__ bv)
{
    const float* __restrict__ W    = blockIdx.z ? Wv : Wq;
    const float* __restrict__ bias = blockIdx.z ? bv : bq;
    float* __restrict__ out        = blockIdx.z ? g_v : g_q;

    __shared__ __half As[2][128][AKP];
    __shared__ __half Bs[2][PKB][BNP];

    const int tid  = threadIdx.x;
    const int lane = tid & 31;
    const int wid  = tid >> 5;
    const int gid  = lane >> 2;
    const int tig  = lane & 3;
    const int m0   = blockIdx.y * 128;
    const int n0   = blockIdx.x * 128;

    const int mBase = (wid >> 2) * 64;
    const int nBase = (wid & 3) * 32;

    const int a_row = (lane & 7) + 8 * ((lane >> 3) & 1);
    const int a_col = 8 * (lane >> 4);
    const int b_row = lane & 15;

    float c[4][4][4];
    #pragma unroll
    for (int f = 0; f < 4; f++)
        #pragma unroll
        for (int g = 0; g < 4; g++)
            #pragma unroll
            for (int i = 0; i < 4; i++) c[f][g][i] = 0.0f;

    uint2 pa[4], pb[4];

    #pragma unroll
    for (int p = 0; p < 4; p++) {
        int s = tid + 256 * p;
        int m = s >> 3, kq = s & 7;
        pa[p] = f4_to_h4(*(const float4*)(A + (size_t)(m0 + m) * HID + 4 * kq));
        int kr = s >> 5, nq = s & 31;
        pb[p] = f4_to_h4(*(const float4*)(W + (size_t)kr * HID + n0 + 4 * nq));
    }
    #pragma unroll
    for (int p = 0; p < 4; p++) {
        int s = tid + 256 * p;
        int m = s >> 3, kq = s & 7;
        *(uint2*)&As[0][m][4 * kq] = pa[p];
        int kr = s >> 5, nq = s & 31;
        *(uint2*)&Bs[0][kr][4 * nq] = pb[p];
    }
    __syncthreads();

    const int NKB = HID / PKB;
    for (int kb = 0; kb < NKB; kb++) {
        const int cur = kb & 1;
        const int nxt = cur ^ 1;

        if (kb + 1 < NKB) {
            const int kk = (kb + 1) * PKB;
            #pragma unroll
            for (int p = 0; p < 4; p++) {
                int s = tid + 256 * p;
                int m = s >> 3, kq = s & 7;
                pa[p] = f4_to_h4(*(const float4*)(A + (size_t)(m0 + m) * HID + kk + 4 * kq));
                int kr = s >> 5, nq = s & 31;
                pb[p] = f4_to_h4(*(const float4*)(W + (size_t)(kk + kr) * HID + n0 + 4 * nq));
            }
        }

        #pragma unroll
        for (int ks = 0; ks < PKB; ks += 16) {
            uint32_t a[4][4], b[4][2];
            #pragma unroll
            for (int f = 0; f < 4; f++)
                ldsm_x4(a[f][0], a[f][1], a[f][2], a[f][3],
                        &As[cur][mBase + 16 * f + a_row][ks + a_col]);
            #pragma unroll
            for (int g = 0; g < 4; g++)
                ldsm_x2_trans(b[g][0], b[g][1],
                              &Bs[cur][ks + b_row][nBase + 8 * g]);
            #pragma unroll
            for (int f = 0; f < 4; f++)
                #pragma unroll
                for (int g = 0; g < 4; g++)
                    mma_f16(c[f][g], a[f], b[g]);
        }

        if (kb + 1 < NKB) {
            #pragma unroll
            for (int p = 0; p < 4; p++) {
                int s = tid + 256 * p;
                int m = s >> 3, kq = s & 7;
                *(uint2*)&As[nxt][m][4 * kq] = pa[p];
                int kr = s >> 5, nq = s & 31;
                *(uint2*)&Bs[nxt][kr][4 * nq] = pb[p];
            }
        }
        __syncthreads();
    }

    #pragma unroll
    for (int g = 0; g < 4; g++) {
        const int n  = n0 + nBase + 8 * g + 2 * tig;
        const int h  = n >> 6;
        const int cc = n & 63;
        const float b0 = bias[n];
        const float b1 = bias[n + 1];
        #pragma unroll
        for (int f = 0; f < 4; f++) {
            #pragma unroll
            for (int half = 0; half < 2; half++) {
                int m  = m0 + mBase + 16 * f + gid + 8 * half;
                int bb = m >> 11;
                int s  = m & 2047;
                float2 o;
                o.x = c[f][g][2 * half + 0] + b0;
                o.y = c[f][g][2 * half + 1] + b1;
                *(float2*)(out + (((size_t)(bb * NH + h) * S2 + s) * HD + cc)) = o;
            }
        }
    }
}

// ---------------------------------------------------------------------------
// Tensor-core sparse attention.
// Dense score GEMM (32x160x64) and dense ctx GEMM (32x64x160) on fp16 mma;
// softmax in fp32; strided (t>=2) keys scalar with t-outer interleaved chains.
// smem (61,952 B -> 3 CTAs/SM):
//   KVu:  Kh fp16 [64][176] (k-major)  UNION  Vh fp16 [160][72]
//   Qh:   fp16 [32][72]
//   Ps:   fp32 [32][168]               UNION  Cstr fp32 [32][64]
//   Ph:   fp16 [32][168]  (normalized probs for ctx mma)
//   Sstr: fp32 [32][16]
// Masked entries are exactly 0 after softmax (fp32 exp underflow) -> exact.
// ---------------------------------------------------------------------------
#define TQ    32
#define WIN   160
#define KP    176   // Kh pitch (halves), 22x16B: 8-row ldmatrix conflict-free
#define VP    72    // Vh pitch (halves), 9x16B odd
#define QP    72    // Qh pitch (halves)
#define PSP   168   // Ps pitch (floats)
#define PHP   168   // Ph pitch (halves), 21x16B odd

#define OFF_QH   23040
#define OFF_PS   27648
#define OFF_PH   49152
#define OFF_SSTR 59904
#define ATTN_SMEM_BYTES 61952

__global__ __launch_bounds__(256, 3)
void attn_kernel(const float* __restrict__ amask, float* __restrict__ out)
{
    extern __shared__ char sm[];
    __half* Kh   = (__half*)sm;                 // [64][176]
    __half* Vh   = (__half*)sm;                 // [160][72]  (union)
    __half* Qh   = (__half*)(sm + OFF_QH);      // [32][72]
    float*  Ps   = (float*)(sm + OFF_PS);       // [32][168]
    float*  Cstr = (float*)(sm + OFF_PS);       // [32][64]   (union, after Ps dead)
    __half* Ph   = (__half*)(sm + OFF_PH);      // [32][168]
    float*  Sstr = (float*)(sm + OFF_SSTR);     // [32][16]

    const int tid  = threadIdx.x;
    const int tx   = tid & 31;
    const int ty   = tid >> 5;          // warp id 0..7
    const int gid  = tx >> 2;
    const int tig  = tx & 3;
    const int I0   = blockIdx.x * TQ;
    const int bh   = blockIdx.y;
    const int b    = bh >> 4;
    const int jbase = I0 - 128;
    const int nstr  = I0 >> 7;          // uniform across the 32-row tile

    const float* __restrict__ q  = g_q + (size_t)bh * S2 * HD;
    const float* __restrict__ v  = g_v + (size_t)bh * S2 * HD;
    const float* __restrict__ am = amask + b * S2;

    // mma warp tiling
    const int m0w = (ty >> 2) * 16;     // 0 or 16
    const int a_row = (tx & 7) + 8 * ((tx >> 3) & 1);
    const int a_col = 8 * (tx >> 4);
    const int b_row = tx & 15;

    // ---- stage 1: Qh fp16 [r][72], Kh fp16 transposed [d][176] ----
    for (int idx = tid; idx < TQ * 32; idx += 256) {
        int r = idx >> 5, dq = idx & 31;
        float2 val = *(const float2*)(q + (size_t)(I0 + r) * HD + 2 * dq);
        *(__half2*)&Qh[r * QP + 2 * dq] = __float22half2_rn(val);
    }
    for (int idx = tid; idx < WIN * HD; idx += 256) {
        int c = idx >> 6, d = idx & 63;
        int j = jbase + c;
        float val = (j >= 0) ? q[(size_t)j * HD + d] : 0.0f;
        Kh[d * KP + c] = __float2half(val);
    }
    __syncthreads();

    // ---- stage 2: score mma, warp covers m16 x n40 (5 tiles) ----
    {
        const int n0w = (ty & 3) * 40;
        float cfr[5][4];
        #pragma unroll
        for (int t = 0; t < 5; t++)
            #pragma unroll
            for (int i = 0; i < 4; i++) cfr[t][i] = 0.0f;

        #pragma unroll
        for (int kk = 0; kk < 64; kk += 16) {
            uint32_t a[4];
            ldsm_x4(a[0], a[1], a[2], a[3], &Qh[(m0w + a_row) * QP + kk + a_col]);
            #pragma unroll
            for (int t = 0; t < 5; t++) {
                uint32_t bb[2];
                ldsm_x2_trans(bb[0], bb[1], &Kh[(kk + b_row) * KP + n0w + 8 * t]);
                mma_f16(cfr[t], a, bb);
            }
        }

        // epilogue: scale + mask + attention_mask -> Ps fp32
        #pragma unroll
        for (int t = 0; t < 5; t++) {
            int c0 = n0w + 8 * t + 2 * tig;
            int j0 = jbase + c0;
            float am0 = 0.0f, am1 = 0.0f;
            if (j0 >= 0) { float2 a2 = *(const float2*)(am + j0); am0 = a2.x; am1 = a2.y; }
            #pragma unroll
            for (int h = 0; h < 2; h++) {
                int r = m0w + gid + 8 * h;
                bool ok0 = (c0 >= r)     && (c0 <= r + 128)     && (j0 >= 0);
                bool ok1 = (c0 + 1 >= r) && (c0 + 1 <= r + 128) && (j0 >= 0);
                float2 sv;
                sv.x = ok0 ? cfr[t][2 * h + 0] * 0.125f + am0 : -CUDART_INF_F;
                sv.y = ok1 ? cfr[t][2 * h + 1] * 0.125f + am1 : -CUDART_INF_F;
                *(float2*)&Ps[r * PSP + c0] = sv;
            }
        }
    }
    __syncthreads();   // Kh dead, Ps complete

    // ---- stage 3: Vh staging + strided scores (t-outer, 4 chains) ----
    for (int idx = tid; idx < WIN * 32; idx += 256) {
        int c = idx >> 5, dq = idx & 31;
        int j = jbase + c;
        float2 val = (j >= 0) ? *(const float2*)(v + (size_t)j * HD + 2 * dq)
                              : make_float2(0.f, 0.f);
        *(__half2*)&Vh[c * VP + 2 * dq] = __float22half2_rn(val);
    }

    {
        float2 qr[4];
        #pragma unroll
        for (int qi = 0; qi < 4; qi++)
            qr[qi] = *(const float2*)(q + (size_t)(I0 + 4 * ty + qi) * HD + 2 * tx);

        for (int t = 2; t <= nstr; t++) {
            float p[4];
            #pragma unroll
            for (int qi = 0; qi < 4; qi++) {
                int j = I0 + 4 * ty + qi - (t << 7);
                float2 k2 = *(const float2*)(q + (size_t)j * HD + 2 * tx);
                p[qi] = qr[qi].x * k2.x + qr[qi].y * k2.y;
            }
            #pragma unroll
            for (int off = 16; off >= 1; off >>= 1)
                #pragma unroll
                for (int qi = 0; qi < 4; qi++)
                    p[qi] += __shfl_xor_sync(0xffffffffu, p[qi], off);
            if (tx == 0) {
                #pragma unroll
                for (int qi = 0; qi < 4; qi++) {
                    int j = I0 + 4 * ty + qi - (t << 7);
                    Sstr[(4 * ty + qi) * 16 + t] = p[qi] * 0.125f + am[j];
                }
            }
        }
    }
    __syncthreads();   // Sstr ready

    // ---- stage 4: softmax (fp32) -> Ph fp16 normalized, pnv regs ----
    float pnv[4];
    #pragma unroll
    for (int qi = 0; qi < 4; qi++) {
        int r = 4 * ty + qi;

        float mx = -CUDART_INF_F;
        #pragma unroll
        for (int u = 0; u < 5; u++) mx = fmaxf(mx, Ps[r * PSP + tx + 32 * u]);
        if (tx + 2 <= nstr) mx = fmaxf(mx, Sstr[r * 16 + tx + 2]);
        mx = fmaxf(mx, __shfl_xor_sync(0xffffffffu, mx, 16));
        mx = fmaxf(mx, __shfl_xor_sync(0xffffffffu, mx, 8));
        mx = fmaxf(mx, __shfl_xor_sync(0xffffffffu, mx, 4));
        mx = fmaxf(mx, __shfl_xor_sync(0xffffffffu, mx, 2));
        mx = fmaxf(mx, __shfl_xor_sync(0xffffffffu, mx, 1));

        float e[5];
        float s = 0.0f;
        #pragma unroll
        for (int u = 0; u < 5; u++) {
            e[u] = __expf(Ps[r * PSP + tx + 32 * u] - mx);
            s += e[u];
        }
        float es = (tx + 2 <= nstr) ? __expf(Sstr[r * 16 + tx + 2] - mx) : 0.0f;
        s += es;
        s += __shfl_xor_sync(0xffffffffu, s, 16);
        s += __shfl_xor_sync(0xffffffffu, s, 8);
        s += __shfl_xor_sync(0xffffffffu, s, 4);
        s += __shfl_xor_sync(0xffffffffu, s, 2);
        s += __shfl_xor_sync(0xffffffffu, s, 1);
        float inv = 1.0f / s;
        pnv[qi] = es * inv;

        #pragma unroll
        for (int u = 0; u < 5; u++)
            Ph[r * PHP + tx + 32 * u] = __float2half(e[u] * inv);
    }
    __syncthreads();   // Ps dead -> Cstr writable; Ph + Vh ready

    // ---- stage 5: strided ctx (t-outer) -> Cstr ----
    {
        float ax[4] = {0.f, 0.f, 0.f, 0.f};
        float ay[4] = {0.f, 0.f, 0.f, 0.f};
        for (int t = 2; t <= nstr; t++) {
            #pragma unroll
            for (int qi = 0; qi < 4; qi++) {
                float p = __shfl_sync(0xffffffffu, pnv[qi], t - 2);
                int j = I0 + 4 * ty + qi - (t << 7);
                float2 v2 = *(const float2*)(v + (size_t)j * HD + 2 * tx);
                ax[qi] = fmaf(p, v2.x, ax[qi]);
                ay[qi] = fmaf(p, v2.y, ay[qi]);
            }
        }
        #pragma unroll
        for (int qi = 0; qi < 4; qi++) {
            float2 cst; cst.x = ax[qi]; cst.y = ay[qi];
            *(float2*)&Cstr[(4 * ty + qi) * 64 + 2 * tx] = cst;
        }
    }
    __syncthreads();   // Cstr ready

    // ---- stage 6: ctx mma, warp covers m16 x n16 (2 tiles), K=160 ----
    {
        const int n0w = (ty & 3) * 16;
        float ofr[2][4];
        #pragma unroll
        for (int t = 0; t < 2; t++)
            #pragma unroll
            for (int i = 0; i < 4; i++) ofr[t][i] = 0.0f;

        #pragma unroll
        for (int kk = 0; kk < WIN; kk += 16) {
            uint32_t a[4];
            ldsm_x4(a[0], a[1], a[2], a[3], &Ph[(m0w + a_row) * PHP + kk + a_col]);
            #pragma unroll
            for (int t = 0; t < 2; t++) {
                uint32_t bb[2];
                ldsm_x2_trans(bb[0], bb[1], &Vh[(kk + b_row) * VP + n0w + 8 * t]);
                mma_f16(ofr[t], a, bb);
            }
        }

        #pragma unroll
        for (int t = 0; t < 2; t++) {
            int d0 = n0w + 8 * t + 2 * tig;
            #pragma unroll
            for (int h = 0; h < 2; h++) {
                int r = m0w + gid + 8 * h;
                int i = I0 + r;
                float2 cs = *(const float2*)&Cstr[r * 64 + d0];
                float2 res;
                res.x = ofr[t][2 * h + 0] + cs.x;
                res.y = ofr[t][2 * h + 1] + cs.y;
                *(float2*)(out + ((size_t)(b * S2 + i) * (NH * HD)) + (bh & 15) * HD + d0) = res;
            }
        }
    }
}

// ---------------------------------------------------------------------------
// Launch
// Inputs (metadata order): hidden_states, attention_mask, W_q, b_q, W_v, b_v
// ---------------------------------------------------------------------------
extern "C" void kernel_launch(void* const* d_in, const int* in_sizes, int n_in,
                              void* d_out, int out_size)
{
    const float* hidden = (const float*)d_in[0];
    const float* amask  = (const float*)d_in[1];
    const float* Wq     = (const float*)d_in[2];
    const float* bq     = (const float*)d_in[3];
    const float* Wv     = (const float*)d_in[4];
    const float* bv     = (const float*)d_in[5];
    float* out = (float*)d_out;

    cudaFuncSetAttribute(attn_kernel,
                         cudaFuncAttributeMaxDynamicSharedMemorySize,
                         ATTN_SMEM_BYTES);

    dim3 pgrid(HID / 128, (BATCH * S2) / 128, 2);   // (8, 32, 2)
    proj_kernel<<<pgrid, 256>>>(hidden, Wq, bq, Wv, bv);

    dim3 agrid(S2 / TQ, BATCH * NH);                // (64, 32)
    attn_kernel<<<agrid, 256, ATTN_SMEM_BYTES>>>(amask, out);
}

// round 14
// speedup vs baseline: 1.3921x; 1.0478x over previous
#include <cuda_runtime.h>
#include <cuda_fp16.h>
#include <math_constants.h>
#include <cstdint>

// Problem constants
#define S2    2048
#define HID   1024
#define NH    16
#define HD    64
#define BATCH 2

// Scratch for projected Q and V in [B, H, S, d] layout (16 MB each).
__device__ float g_q[BATCH * NH * S2 * HD];
__device__ float g_v[BATCH * NH * S2 * HD];

// ---------------------------------------------------------------------------
// Shared mma/ldmatrix helpers.
// ---------------------------------------------------------------------------
__device__ __forceinline__ uint2 f4_to_h4(float4 v) {
    __half2 h0 = __floats2half2_rn(v.x, v.y);
    __half2 h1 = __floats2half2_rn(v.z, v.w);
    uint2 r;
    r.x = *(uint32_t*)&h0;
    r.y = *(uint32_t*)&h1;
    return r;
}

__device__ __forceinline__ void ldsm_x4(uint32_t& r0, uint32_t& r1,
                                        uint32_t& r2, uint32_t& r3,
                                        const __half* p) {
    uint32_t a = (uint32_t)__cvta_generic_to_shared(p);
    asm volatile("ldmatrix.sync.aligned.m8n8.x4.shared.b16 {%0,%1,%2,%3}, [%4];"
                 : "=r"(r0), "=r"(r1), "=r"(r2), "=r"(r3) : "r"(a));
}

__device__ __forceinline__ void ldsm_x2_trans(uint32_t& r0, uint32_t& r1,
                                              const __half* p) {
    uint32_t a = (uint32_t)__cvta_generic_to_shared(p);
    asm volatile("ldmatrix.sync.aligned.m8n8.x2.trans.shared.b16 {%0,%1}, [%2];"
                 : "=r"(r0), "=r"(r1) : "r"(a));
}

__device__ __forceinline__ void mma_f16(float c[4], const uint32_t a[4],
                                        const uint32_t b[2]) {
    asm volatile(
        "mma.sync.aligned.m16n8k16.row.col.f32.f16.f16.f32 "
        "{%0,%1,%2,%3}, {%4,%5,%6,%7}, {%8,%9}, {%0,%1,%2,%3};"
        : "+f"(c[0]), "+f"(c[1]), "+f"(c[2]), "+f"(c[3])
        : "r"(a[0]), "r"(a[1]), "r"(a[2]), "r"(a[3]), "r"(b[0]), "r"(b[1]));
}

// ---------------------------------------------------------------------------
// FP16 tensor-core projection GEMM (measured; unchanged).
// ---------------------------------------------------------------------------
#define PKB 32
#define AKP 40
#define BNP 136

__global__ __launch_bounds__(256)
void proj_kernel(const float* __restrict__ A,
                 const float* __restrict__ Wq, const float* __restrict__ bq,
                 const float* __restrict__ Wv, const float* __restrict__ bv)
{
    const float* __restrict__ W    = blockIdx.z ? Wv : Wq;
    const float* __restrict__ bias = blockIdx.z ? bv : bq;
    float* __restrict__ out        = blockIdx.z ? g_v : g_q;

    __shared__ __half As[2][128][AKP];
    __shared__ __half Bs[2][PKB][BNP];

    const int tid  = threadIdx.x;
    const int lane = tid & 31;
    const int wid  = tid >> 5;
    const int gid  = lane >> 2;
    const int tig  = lane & 3;
    const int m0   = blockIdx.y * 128;
    const int n0   = blockIdx.x * 128;

    const int mBase = (wid >> 2) * 64;
    const int nBase = (wid & 3) * 32;

    const int a_row = (lane & 7) + 8 * ((lane >> 3) & 1);
    const int a_col = 8 * (lane >> 4);
    const int b_row = lane & 15;

    float c[4][4][4];
    #pragma unroll
    for (int f = 0; f < 4; f++)
        #pragma unroll
        for (int g = 0; g < 4; g++)
            #pragma unroll
            for (int i = 0; i < 4; i++) c[f][g][i] = 0.0f;

    uint2 pa[4], pb[4];

    #pragma unroll
    for (int p = 0; p < 4; p++) {
        int s = tid + 256 * p;
        int m = s >> 3, kq = s & 7;
        pa[p] = f4_to_h4(*(const float4*)(A + (size_t)(m0 + m) * HID + 4 * kq));
        int kr = s >> 5, nq = s & 31;
        pb[p] = f4_to_h4(*(const float4*)(W + (size_t)kr * HID + n0 + 4 * nq));
    }
    #pragma unroll
    for (int p = 0; p < 4; p++) {
        int s = tid + 256 * p;
        int m = s >> 3, kq = s & 7;
        *(uint2*)&As[0][m][4 * kq] = pa[p];
        int kr = s >> 5, nq = s & 31;
        *(uint2*)&Bs[0][kr][4 * nq] = pb[p];
    }
    __syncthreads();

    const int NKB = HID / PKB;
    for (int kb = 0; kb < NKB; kb++) {
        const int cur = kb & 1;
        const int nxt = cur ^ 1;

        if (kb + 1 < NKB) {
            const int kk = (kb + 1) * PKB;
            #pragma unroll
            for (int p = 0; p < 4; p++) {
                int s = tid + 256 * p;
                int m = s >> 3, kq = s & 7;
                pa[p] = f4_to_h4(*(const float4*)(A + (size_t)(m0 + m) * HID + kk + 4 * kq));
                int kr = s >> 5, nq = s & 31;
                pb[p] = f4_to_h4(*(const float4*)(W + (size_t)(kk + kr) * HID + n0 + 4 * nq));
            }
        }

        #pragma unroll
        for (int ks = 0; ks < PKB; ks += 16) {
            uint32_t a[4][4], b[4][2];
            #pragma unroll
            for (int f = 0; f < 4; f++)
                ldsm_x4(a[f][0], a[f][1], a[f][2], a[f][3],
                        &As[cur][mBase + 16 * f + a_row][ks + a_col]);
            #pragma unroll
            for (int g = 0; g < 4; g++)
                ldsm_x2_trans(b[g][0], b[g][1],
                              &Bs[cur][ks + b_row][nBase + 8 * g]);
            #pragma unroll
            for (int f = 0; f < 4; f++)
                #pragma unroll
                for (int g = 0; g < 4; g++)
                    mma_f16(c[f][g], a[f], b[g]);
        }

        if (kb + 1 < NKB) {
            #pragma unroll
            for (int p = 0; p < 4; p++) {
                int s = tid + 256 * p;
                int m = s >> 3, kq = s & 7;
                *(uint2*)&As[nxt][m][4 * kq] = pa[p];
                int kr = s >> 5, nq = s & 31;
                *(uint2*)&Bs[nxt][kr][4 * nq] = pb[p];
            }
        }
        __syncthreads();
    }

    #pragma unroll
    for (int g = 0; g < 4; g++) {
        const int n  = n0 + nBase + 8 * g + 2 * tig;
        const int h  = n >> 6;
        const int cc = n & 63;
        const float b0 = bias[n];
        const float b1 = bias[n + 1];
        #pragma unroll
        for (int f = 0; f < 4; f++) {
            #pragma unroll
            for (int half = 0; half < 2; half++) {
                int m  = m0 + mBase + 16 * f + gid + 8 * half;
                int bb = m >> 11;
                int s  = m & 2047;
                float2 o;
                o.x = c[f][g][2 * half + 0] + b0;
                o.y = c[f][g][2 * half + 1] + b1;
                *(float2*)(out + (((size_t)(bb * NH + h) * S2 + s) * HD + cc)) = o;
            }
        }
    }
}

// ---------------------------------------------------------------------------
// Tensor-core sparse attention — slimmed to 49,152 B smem, 4 CTAs/SM.
// Aliasing plan (all unions separated by barriers):
//   [0, 23040):        Kh fp16 [64][176]   UNION  Vh fp16 [160][72]
//   [23040, 27648):    Qh fp16 [32][72]    UNION  Sstr fp32 [32][16]
//   [27648, 49152):    Ps fp32 [32][168]   UNION  (Ph fp16 [32][168] @+0,
//                                                  Cstr fp32 [32][64] @+10752)
// Stage 4 reads Ps fully into registers for its rows, barrier, then writes
// normalized fp16 Ph over the Ps region. Barriers: 4 (was 6).
// Masked entries are exactly 0 after softmax (fp32 exp underflow) -> exact.
// ---------------------------------------------------------------------------
#define TQ    32
#define WIN   160
#define KP    176   // Kh pitch (halves)
#define VP    72    // Vh pitch (halves)
#define QP    72    // Qh pitch (halves)
#define PSP   168   // Ps pitch (floats)
#define PHP   168   // Ph pitch (halves)

#define OFF_QH   23040
#define OFF_SSTR 23040
#define OFF_PS   27648
#define OFF_PH   27648
#define OFF_CSTR (27648 + 10752)
#define ATTN_SMEM_BYTES 49152

__global__ __launch_bounds__(256, 4)
void attn_kernel(const float* __restrict__ amask, float* __restrict__ out)
{
    extern __shared__ char sm[];
    __half* Kh   = (__half*)sm;                 // [64][176]
    __half* Vh   = (__half*)sm;                 // [160][72]  (union)
    __half* Qh   = (__half*)(sm + OFF_QH);      // [32][72]
    float*  Sstr = (float*)(sm + OFF_SSTR);     // [32][16]   (union w/ Qh)
    float*  Ps   = (float*)(sm + OFF_PS);       // [32][168]
    __half* Ph   = (__half*)(sm + OFF_PH);      // [32][168]  (union w/ Ps)
    float*  Cstr = (float*)(sm + OFF_CSTR);     // [32][64]   (union w/ Ps tail)

    const int tid  = threadIdx.x;
    const int tx   = tid & 31;
    const int ty   = tid >> 5;          // warp id 0..7
    const int gid  = tx >> 2;
    const int tig  = tx & 3;
    const int I0   = blockIdx.x * TQ;
    const int bh   = blockIdx.y;
    const int b    = bh >> 4;
    const int jbase = I0 - 128;
    const int nstr  = I0 >> 7;          // uniform across the 32-row tile

    const float* __restrict__ q  = g_q + (size_t)bh * S2 * HD;
    const float* __restrict__ v  = g_v + (size_t)bh * S2 * HD;
    const float* __restrict__ am = amask + b * S2;

    // mma warp tiling
    const int m0w = (ty >> 2) * 16;     // 0 or 16
    const int a_row = (tx & 7) + 8 * ((tx >> 3) & 1);
    const int a_col = 8 * (tx >> 4);
    const int b_row = tx & 15;

    // ---- stage 1: Qh fp16 [r][72], Kh fp16 transposed [d][176] ----
    for (int idx = tid; idx < TQ * 32; idx += 256) {
        int r = idx >> 5, dq = idx & 31;
        float2 val = *(const float2*)(q + (size_t)(I0 + r) * HD + 2 * dq);
        *(__half2*)&Qh[r * QP + 2 * dq] = __float22half2_rn(val);
    }
    for (int idx = tid; idx < WIN * HD; idx += 256) {
        int c = idx >> 6, d = idx & 63;
        int j = jbase + c;
        float val = (j >= 0) ? q[(size_t)j * HD + d] : 0.0f;
        Kh[d * KP + c] = __float2half(val);
    }
    __syncthreads();                              // B0: tiles staged

    // ---- stage 2: score mma, warp covers m16 x n40 (5 tiles) ----
    {
        const int n0w = (ty & 3) * 40;
        float cfr[5][4];
        #pragma unroll
        for (int t = 0; t < 5; t++)
            #pragma unroll
            for (int i = 0; i < 4; i++) cfr[t][i] = 0.0f;

        #pragma unroll
        for (int kk = 0; kk < 64; kk += 16) {
            uint32_t a[4];
            ldsm_x4(a[0], a[1], a[2], a[3], &Qh[(m0w + a_row) * QP + kk + a_col]);
            #pragma unroll
            for (int t = 0; t < 5; t++) {
                uint32_t bb[2];
                ldsm_x2_trans(bb[0], bb[1], &Kh[(kk + b_row) * KP + n0w + 8 * t]);
                mma_f16(cfr[t], a, bb);
            }
        }

        // epilogue: scale + mask + attention_mask -> Ps fp32
        #pragma unroll
        for (int t = 0; t < 5; t++) {
            int c0 = n0w + 8 * t + 2 * tig;
            int j0 = jbase + c0;
            float am0 = 0.0f, am1 = 0.0f;
            if (j0 >= 0) { float2 a2 = *(const float2*)(am + j0); am0 = a2.x; am1 = a2.y; }
            #pragma unroll
            for (int h = 0; h < 2; h++) {
                int r = m0w + gid + 8 * h;
                bool ok0 = (c0 >= r)     && (c0 <= r + 128)     && (j0 >= 0);
                bool ok1 = (c0 + 1 >= r) && (c0 + 1 <= r + 128) && (j0 >= 0);
                float2 sv;
                sv.x = ok0 ? cfr[t][2 * h + 0] * 0.125f + am0 : -CUDART_INF_F;
                sv.y = ok1 ? cfr[t][2 * h + 1] * 0.125f + am1 : -CUDART_INF_F;
                *(float2*)&Ps[r * PSP + c0] = sv;
            }
        }
    }
    __syncthreads();                              // B1: Kh+Qh dead, Ps ready

    // ---- stage 3: Vh staging + strided scores (t-outer, 4 chains) ----
    for (int idx = tid; idx < WIN * 32; idx += 256) {
        int c = idx >> 5, dq = idx & 31;
        int j = jbase + c;
        float2 val = (j >= 0) ? *(const float2*)(v + (size_t)j * HD + 2 * dq)
                              : make_float2(0.f, 0.f);
        *(__half2*)&Vh[c * VP + 2 * dq] = __float22half2_rn(val);
    }

    {
        float2 qr[4];
        #pragma unroll
        for (int qi = 0; qi < 4; qi++)
            qr[qi] = *(const float2*)(q + (size_t)(I0 + 4 * ty + qi) * HD + 2 * tx);

        for (int t = 2; t <= nstr; t++) {
            float p[4];
            #pragma unroll
            for (int qi = 0; qi < 4; qi++) {
                int j = I0 + 4 * ty + qi - (t << 7);
                float2 k2 = *(const float2*)(q + (size_t)j * HD + 2 * tx);
                p[qi] = qr[qi].x * k2.x + qr[qi].y * k2.y;
            }
            #pragma unroll
            for (int off = 16; off >= 1; off >>= 1)
                #pragma unroll
                for (int qi = 0; qi < 4; qi++)
                    p[qi] += __shfl_xor_sync(0xffffffffu, p[qi], off);
            if (tx == 0) {
                #pragma unroll
                for (int qi = 0; qi < 4; qi++) {
                    int j = I0 + 4 * ty + qi - (t << 7);
                    Sstr[(4 * ty + qi) * 16 + t] = p[qi] * 0.125f + am[j];
                }
            }
        }
    }
    __syncwarp();   // Sstr is same-warp produce/consume

    // ---- stage 4a: softmax fully in registers (reads Ps + Sstr) ----
    float e[4][5], inv4[4], pnv[4];
    #pragma unroll
    for (int qi = 0; qi < 4; qi++) {
        int r = 4 * ty + qi;

        float mx = -CUDART_INF_F;
        #pragma unroll
        for (int u = 0; u < 5; u++) mx = fmaxf(mx, Ps[r * PSP + tx + 32 * u]);
        if (tx + 2 <= nstr) mx = fmaxf(mx, Sstr[r * 16 + tx + 2]);
        mx = fmaxf(mx, __shfl_xor_sync(0xffffffffu, mx, 16));
        mx = fmaxf(mx, __shfl_xor_sync(0xffffffffu, mx, 8));
        mx = fmaxf(mx, __shfl_xor_sync(0xffffffffu, mx, 4));
        mx = fmaxf(mx, __shfl_xor_sync(0xffffffffu, mx, 2));
        mx = fmaxf(mx, __shfl_xor_sync(0xffffffffu, mx, 1));

        float s = 0.0f;
        #pragma unroll
        for (int u = 0; u < 5; u++) {
            e[qi][u] = __expf(Ps[r * PSP + tx + 32 * u] - mx);
            s += e[qi][u];
        }
        float es = (tx + 2 <= nstr) ? __expf(Sstr[r * 16 + tx + 2] - mx) : 0.0f;
        s += es;
        s += __shfl_xor_sync(0xffffffffu, s, 16);
        s += __shfl_xor_sync(0xffffffffu, s, 8);
        s += __shfl_xor_sync(0xffffffffu, s, 4);
        s += __shfl_xor_sync(0xffffffffu, s, 2);
        s += __shfl_xor_sync(0xffffffffu, s, 1);
        inv4[qi] = 1.0f / s;
        pnv[qi]  = es * inv4[qi];
    }
    __syncthreads();   // B2: all Ps reads done -> Ph/Cstr may overwrite region

    // ---- stage 4b: write normalized fp16 probs over the Ps region ----
    #pragma unroll
    for (int qi = 0; qi < 4; qi++) {
        int r = 4 * ty + qi;
        #pragma unroll
        for (int u = 0; u < 5; u++)
            Ph[r * PHP + tx + 32 * u] = __float2half(e[qi][u] * inv4[qi]);
    }

    // ---- stage 5: strided ctx (t-outer) -> Cstr ----
    {
        float ax[4] = {0.f, 0.f, 0.f, 0.f};
        float ay[4] = {0.f, 0.f, 0.f, 0.f};
        for (int t = 2; t <= nstr; t++) {
            #pragma unroll
            for (int qi = 0; qi < 4; qi++) {
                float p = __shfl_sync(0xffffffffu, pnv[qi], t - 2);
                int j = I0 + 4 * ty + qi - (t << 7);
                float2 v2 = *(const float2*)(v + (size_t)j * HD + 2 * tx);
                ax[qi] = fmaf(p, v2.x, ax[qi]);
                ay[qi] = fmaf(p, v2.y, ay[qi]);
            }
        }
        #pragma unroll
        for (int qi = 0; qi < 4; qi++) {
            float2 cst; cst.x = ax[qi]; cst.y = ay[qi];
            *(float2*)&Cstr[(4 * ty + qi) * 64 + 2 * tx] = cst;
        }
    }
    __syncthreads();   // B3: Ph + Cstr + Vh ready

    // ---- stage 6: ctx mma, warp covers m16 x n16 (2 tiles), K=160 ----
    {
        const int n0w = (ty & 3) * 16;
        float ofr[2][4];
        #pragma unroll
        for (int t = 0; t < 2; t++)
            #pragma unroll
            for (int i = 0; i < 4; i++) ofr[t][i] = 0.0f;

        #pragma unroll
        for (int kk = 0; kk < WIN; kk += 16) {
            uint32_t a[4];
            ldsm_x4(a[0], a[1], a[2], a[3], &Ph[(m0w + a_row) * PHP + kk + a_col]);
            #pragma unroll
            for (int t = 0; t < 2; t++) {
                uint32_t bb[2];
                ldsm_x2_trans(bb[0], bb[1], &Vh[(kk + b_row) * VP + n0w + 8 * t]);
                mma_f16(ofr[t], a, bb);
            }
        }

        #pragma unroll
        for (int t = 0; t < 2; t++) {
            int d0 = n0w + 8 * t + 2 * tig;
            #pragma unroll
            for (int h = 0; h < 2; h++) {
                int r = m0w + gid + 8 * h;
                int i = I0 + r;
                float2 cs = *(const float2*)&Cstr[r * 64 + d0];
                float2 res;
                res.x = ofr[t][2 * h + 0] + cs.x;
                res.y = ofr[t][2 * h + 1] + cs.y;
                *(float2*)(out + ((size_t)(b * S2 + i) * (NH * HD)) + (bh & 15) * HD + d0) = res;
            }
        }
    }
}

// ---------------------------------------------------------------------------
// Launch
// Inputs (metadata order): hidden_states, attention_mask, W_q, b_q, W_v, b_v
// ---------------------------------------------------------------------------
extern "C" void kernel_launch(void* const* d_in, const int* in_sizes, int n_in,
                              void* d_out, int out_size)
{
    const float* hidden = (const float*)d_in[0];
    const float* amask  = (const float*)d_in[1];
    const float* Wq     = (const float*)d_in[2];
    const float* bq     = (const float*)d_in[3];
    const float* Wv     = (const float*)d_in[4];
    const float* bv     = (const float*)d_in[5];
    float* out = (float*)d_out;

    cudaFuncSetAttribute(attn_kernel,
                         cudaFuncAttributeMaxDynamicSharedMemorySize,
                         ATTN_SMEM_BYTES);

    dim3 pgrid(HID / 128, (BATCH * S2) / 128, 2);   // (8, 32, 2)
    proj_kernel<<<pgrid, 256>>>(hidden, Wq, bq, Wv, bv);

    dim3 agrid(S2 / TQ, BATCH * NH);                // (64, 32)
    attn_kernel<<<agrid, 256, ATTN_SMEM_BYTES>>>(amask, out);
}